// round 1
// baseline (speedup 1.0000x reference)
#include <cuda_runtime.h>

#define L_SEQ   4096
#define BSZ     8
#define DIM     1024
#define NDIM    16
#define CHUNK   512
#define NCHUNK  (L_SEQ / CHUNK)   // 8
#define WARM    256               // q^256 <= 7.5e-12 -> truncation invisible at fp32
#define STRIDE  (BSZ * DIM)       // 8192 floats per timestep

// Per-(d,n) precomputed decay q and output weight c, laid out [n][d] so that
// consecutive threads (consecutive d) load coalesced.
__device__ float g_q[NDIM * DIM];
__device__ float g_c[NDIM * DIM];

__global__ void ema_params_kernel(const float* __restrict__ delta,
                                  const float* __restrict__ alpha,
                                  const float* __restrict__ beta,
                                  const float* __restrict__ gamma) {
    int idx = blockIdx.x * blockDim.x + threadIdx.x;   // idx = n*DIM + d
    if (idx >= NDIM * DIM) return;
    int d = idx & (DIM - 1);
    int n = idx >> 10;

    float e = expf(delta[d]);
    float a = alpha[d * NDIM + n];
    float p = e / (1.0f + 0.5f * e * a);
    g_q[idx] = 1.0f - p * a;                               // in (0, ~0.905)
    g_c[idx] = p * beta[d * NDIM + n] * gamma[d * NDIM + n];
}

__global__ void __launch_bounds__(256)
ema_scan_kernel(const float* __restrict__ x,
                const float* __restrict__ omega,
                float* __restrict__ out) {
    int lin = blockIdx.x * blockDim.x + threadIdx.x;   // B*DIM*NCHUNK threads
    int d = lin & (DIM - 1);
    int r = lin >> 10;
    int b = r & (BSZ - 1);
    int c = r >> 3;                                    // chunk id 0..7

    float q[NDIM], cc[NDIM], h[NDIM];
#pragma unroll
    for (int n = 0; n < NDIM; ++n) {
        q[n]  = g_q[n * DIM + d];
        cc[n] = g_c[n * DIM + d];
        h[n]  = 0.0f;
    }
    float om = omega[d];

    const float* xp = x   + b * DIM + d;
    float*       op = out + b * DIM + d;

    int l0 = c * CHUNK;
    int lw = l0 - WARM;
    if (lw < 0) lw = 0;

    // Warm-up: rebuild state from the decay horizon. No outputs.
#pragma unroll 8
    for (int l = lw; l < l0; ++l) {
        float xv = __ldg(xp + l * STRIDE);
#pragma unroll
        for (int n = 0; n < NDIM; ++n)
            h[n] = fmaf(q[n], h[n], xv);
    }

    // Main: update 16 states, reduce with a 4-way partial tree (keeps the
    // accumulation dependence chain at 4 FMAs, not 16), add residual, store.
#pragma unroll 4
    for (int l = l0; l < l0 + CHUNK; ++l) {
        float xv = __ldg(xp + l * STRIDE);
        float y0 = 0.f, y1 = 0.f, y2 = 0.f, y3 = 0.f;
#pragma unroll
        for (int n = 0; n < NDIM; n += 4) {
            h[n + 0] = fmaf(q[n + 0], h[n + 0], xv);
            h[n + 1] = fmaf(q[n + 1], h[n + 1], xv);
            h[n + 2] = fmaf(q[n + 2], h[n + 2], xv);
            h[n + 3] = fmaf(q[n + 3], h[n + 3], xv);
            y0 = fmaf(cc[n + 0], h[n + 0], y0);
            y1 = fmaf(cc[n + 1], h[n + 1], y1);
            y2 = fmaf(cc[n + 2], h[n + 2], y2);
            y3 = fmaf(cc[n + 3], h[n + 3], y3);
        }
        op[l * STRIDE] = (y0 + y1) + (y2 + y3) + om * xv;
    }
}

extern "C" void kernel_launch(void* const* d_in, const int* in_sizes, int n_in,
                              void* d_out, int out_size) {
    const float* x     = (const float*)d_in[0];
    const float* delta = (const float*)d_in[1];
    const float* alpha = (const float*)d_in[2];
    const float* beta  = (const float*)d_in[3];
    const float* gamma = (const float*)d_in[4];
    const float* omega = (const float*)d_in[5];
    float* out = (float*)d_out;

    ema_params_kernel<<<(NDIM * DIM + 255) / 256, 256>>>(delta, alpha, beta, gamma);

    int total = BSZ * DIM * NCHUNK;                    // 65536 threads
    ema_scan_kernel<<<total / 256, 256>>>(x, omega, out);
}

// round 4
// speedup vs baseline: 2.3118x; 2.3118x over previous
#include <cuda_runtime.h>

#define L_SEQ   4096
#define BSZ     8
#define DIM     1024
#define NDIM    16
#define CHUNK   256
#define NCHUNK  (L_SEQ / CHUNK)   // 16
#define WARM    192               // q^192 ~ 4.7e-9 -> truncation invisible at fp32
#define GRP     8                 // load-batch depth (MLP)
#define STRIDE  (BSZ * DIM)       // 8192 floats per timestep

// Per-(d,n) decay q and output weight c, laid out [n][d] for coalesced loads.
__device__ float g_q[NDIM * DIM];
__device__ float g_c[NDIM * DIM];

__global__ void ema_params_kernel(const float* __restrict__ delta,
                                  const float* __restrict__ alpha,
                                  const float* __restrict__ beta,
                                  const float* __restrict__ gamma) {
    int idx = blockIdx.x * blockDim.x + threadIdx.x;   // idx = n*DIM + d
    if (idx >= NDIM * DIM) return;
    int d = idx & (DIM - 1);
    int n = idx >> 10;

    float e = expf(delta[d]);
    float a = alpha[d * NDIM + n];
    float p = e / (1.0f + 0.5f * e * a);
    g_q[idx] = 1.0f - p * a;                               // in (0, ~0.905)
    g_c[idx] = p * beta[d * NDIM + n] * gamma[d * NDIM + n];
}

__global__ void __launch_bounds__(128)
ema_scan_kernel(const float* __restrict__ x,
                const float* __restrict__ omega,
                float* __restrict__ out) {
    int lin = blockIdx.x * blockDim.x + threadIdx.x;   // B*DIM*NCHUNK threads
    int d = lin & (DIM - 1);
    int r = lin >> 10;
    int b = r & (BSZ - 1);
    int c = r >> 3;                                    // chunk id 0..NCHUNK-1

    float q[NDIM], cc[NDIM], h[NDIM];
#pragma unroll
    for (int n = 0; n < NDIM; ++n) {
        q[n]  = g_q[n * DIM + d];
        cc[n] = g_c[n * DIM + d];
        h[n]  = 0.0f;
    }
    float om = omega[d];

    const float* xp = x   + b * DIM + d;
    float*       op = out + b * DIM + d;

    int l0 = c * CHUNK;
    int lw = l0 - WARM;
    if (lw < 0) lw = 0;          // chunk 0: no warm-up (lw == l0 == 0)

    // ---- Warm-up: rebuild decayed state; batch GRP loads for MLP ----
    for (int g = lw; g < l0; g += GRP) {
        float xv[GRP];
#pragma unroll
        for (int j = 0; j < GRP; ++j)
            xv[j] = __ldg(xp + (g + j) * STRIDE);
#pragma unroll
        for (int j = 0; j < GRP; ++j) {
#pragma unroll
            for (int n = 0; n < NDIM; ++n)
                h[n] = fmaf(q[n], h[n], xv[j]);
        }
    }

    // ---- Main: batch GRP loads, then update + 4-way reduce + store ----
    for (int g = l0; g < l0 + CHUNK; g += GRP) {
        float xv[GRP];
#pragma unroll
        for (int j = 0; j < GRP; ++j)
            xv[j] = __ldg(xp + (g + j) * STRIDE);
#pragma unroll
        for (int j = 0; j < GRP; ++j) {
            float v = xv[j];
            float y0 = 0.f, y1 = 0.f, y2 = 0.f, y3 = 0.f;
#pragma unroll
            for (int n = 0; n < NDIM; n += 4) {
                h[n + 0] = fmaf(q[n + 0], h[n + 0], v);
                h[n + 1] = fmaf(q[n + 1], h[n + 1], v);
                h[n + 2] = fmaf(q[n + 2], h[n + 2], v);
                h[n + 3] = fmaf(q[n + 3], h[n + 3], v);
                y0 = fmaf(cc[n + 0], h[n + 0], y0);
                y1 = fmaf(cc[n + 1], h[n + 1], y1);
                y2 = fmaf(cc[n + 2], h[n + 2], y2);
                y3 = fmaf(cc[n + 3], h[n + 3], y3);
            }
            op[(g + j) * STRIDE] = (y0 + y1) + (y2 + y3) + om * v;
        }
    }
}

extern "C" void kernel_launch(void* const* d_in, const int* in_sizes, int n_in,
                              void* d_out, int out_size) {
    const float* x     = (const float*)d_in[0];
    const float* delta = (const float*)d_in[1];
    const float* alpha = (const float*)d_in[2];
    const float* beta  = (const float*)d_in[3];
    const float* gamma = (const float*)d_in[4];
    const float* omega = (const float*)d_in[5];
    float* out = (float*)d_out;

    ema_params_kernel<<<(NDIM * DIM + 255) / 256, 256>>>(delta, alpha, beta, gamma);

    int total = BSZ * DIM * NCHUNK;                    // 131072 threads
    ema_scan_kernel<<<total / 128, 128>>>(x, omega, out);
}